// round 8
// baseline (speedup 1.0000x reference)
#include <cuda_runtime.h>
#include <cstdint>

// Problem shape (fixed by reference setup_inputs)
#define BB 8
#define NN 32768
#define DD 128
#define HH 64
#define CC 64
#define TOK (BB*NN)
#define NSEG (BB*CC)

#define PITCH 136              // feature tile row pitch (floats)
#define TILE_T 64              // tokens per tile
#define TILES 8                // tiles per CTA -> 512 tokens
#define CTA_T 512
#define NCTA (TOK/CTA_T)       // 512 CTAs, 64 per batch

// smem layout (float-word offsets)
#define SW_A    0              // W1 fp16x2 [h 64][kpair 66] : 4224
#define S_TILE0 4224           // tile buf0 : 64*136 = 8704
#define S_TILE1 12928          // tile buf1
#define S_PART  21632          // MLP partials [4 hq][64 tok] : 256
#define S_E     21888          // e per CTA token : 512
#define S_CL    22400          // cluster per CTA token : 512
#define S_SORT  22912          // sorted (tok|cl<<16, e) float2[512] : 1024
#define S_HIST  23936          // 64
#define S_CUR   24000          // 64
#define S_DEN   24064          // 64
#define S_W2    24128          // 64
#define S_B1    24192          // 64
#define S_END   24256          // 97024 bytes -> 2 CTAs/SM

__device__ float g_denom[NSEG];

// ---------------------------------------------------------------------------
__global__ void init_kernel(float* __restrict__ out) {
    int i = blockIdx.x * blockDim.x + threadIdx.x;
    if (i < NSEG * DD) out[i] = 0.0f;
    if (i < NSEG) g_denom[i] = 0.0f;
}

__global__ void dummy_kernel() {}   // park fused_kernel at ncu capture slot #4

__device__ __forceinline__ uint32_t pack_f16x2(float lo, float hi) {
    uint32_t d;
    asm("cvt.rn.f16x2.f32 %0, %1, %2;" : "=r"(d) : "f"(hi), "f"(lo));
    return d;
}

#define MMA_F16(d, a0,a1,a2,a3, b0,b1)                                         \
    asm volatile(                                                              \
        "mma.sync.aligned.m16n8k16.row.col.f32.f16.f16.f32 "                   \
        "{%0,%1,%2,%3}, {%4,%5,%6,%7}, {%8,%9}, {%0,%1,%2,%3};\n"              \
        : "+f"(d[0]), "+f"(d[1]), "+f"(d[2]), "+f"(d[3])                       \
        : "r"(a0), "r"(a1), "r"(a2), "r"(a3), "r"(b0), "r"(b1))

// stage one 64x128 f32 tile -> smem pitch 136 (2048 float4, 8 per thread)
__device__ __forceinline__ void stage_tile(const float* __restrict__ src,
                                           float* __restrict__ dst, int tid) {
    #pragma unroll
    for (int j = 0; j < 8; j++) {
        const int e = tid + 256 * j;
        const int row = e >> 5, c4 = e & 31;
        uint32_t d = (uint32_t)__cvta_generic_to_shared(dst + row * PITCH + c4 * 4);
        asm volatile("cp.async.cg.shared.global [%0], [%1], 16;"
                     :: "r"(d), "l"(src + row * DD + c4 * 4));
    }
    asm volatile("cp.async.commit_group;");
}

// ---------------------------------------------------------------------------
// Fused single-pass kernel. Per CTA (512 contiguous tokens):
//  Phase 1 (8 tiles, double-buffered cp.async): fp16 m16n8k16 MLP -> e,cl/token
//  Phase 2: in-smem counting sort of 512 tokens by cluster (~runs of len ~8)
//  Phase 3: warp = (token-half, 32-dim slice) walks sorted list; register
//           run-accumulator, one atomicAdd-flush per cluster run. Feature
//           re-reads hit L2 (rows read by phase 1 moments earlier).
// ---------------------------------------------------------------------------
__global__ __launch_bounds__(256, 2) void fused_kernel(
    const float* __restrict__ feat, const int* __restrict__ assign,
    const float* __restrict__ W1, const float* __restrict__ b1,
    const float* __restrict__ W2, const float* __restrict__ b2,
    float* __restrict__ out)
{
    extern __shared__ float smem[];
    uint32_t* swA   = reinterpret_cast<uint32_t*>(smem + SW_A);  // [h][kpair] pitch 66
    float*  spart = smem + S_PART;
    float*  se    = smem + S_E;
    int*    scl   = reinterpret_cast<int*>(smem + S_CL);
    float2* ssort = reinterpret_cast<float2*>(smem + S_SORT);
    int*    hist  = reinterpret_cast<int*>(smem + S_HIST);
    int*    cur   = reinterpret_cast<int*>(smem + S_CUR);
    float*  sden  = smem + S_DEN;
    float*  sW2   = smem + S_W2;
    float*  sb1   = smem + S_B1;

    const int tid  = threadIdx.x;
    const int warp = tid >> 5, lane = tid & 31;
    const int g = lane >> 2, t = lane & 3;
    const int th = warp & 1;        // phase1: 32-token half of tile
    const int hq = warp >> 1;       // phase1: hidden quarter (16 rows)

    const int batch  = blockIdx.x >> 6;
    const int ctaTok = blockIdx.x * CTA_T;
    const float* fbase = feat + (size_t)ctaTok * DD;

    stage_tile(fbase, smem + S_TILE0, tid);       // prologue: tile 0

    // W1 -> fp16x2 pairs: swA[h*66 + p] = {W1[2p][h], W1[2p+1][h]}
    for (int i = tid; i < HH * (DD / 2); i += 256) {
        int p = i >> 6, h = i & 63;
        swA[h * 66 + p] = pack_f16x2(W1[(2 * p) * HH + h],
                                     (2 * p + 1) * HH + h >= 0 ? W1[(2 * p + 1) * HH + h] : 0.0f);
    }
    if (tid < HH) { sW2[tid] = W2[tid]; sb1[tid] = b1[tid]; }
    if (tid < CC) { sden[tid] = 0.0f; hist[tid] = 0; }
    __syncthreads();

    const float w2r0 = sW2[16 * hq + g],     w2r1 = sW2[16 * hq + 8 + g];
    const float b1r0 = sb1[16 * hq + g],     b1r1 = sb1[16 * hq + 8 + g];
    const float b2v  = __ldg(b2);

    // ======================= Phase 1: MLP ====================================
    for (int tl = 0; tl < TILES; tl++) {
        const int buf = tl & 1;
        if (tl + 1 < TILES) {
            stage_tile(fbase + (size_t)(tl + 1) * TILE_T * DD,
                       smem + (buf ? S_TILE0 : S_TILE1), tid);
            asm volatile("cp.async.wait_group 1;");
        } else {
            asm volatile("cp.async.wait_group 0;");
        }
        __syncthreads();

        const float* tb = smem + (buf ? S_TILE1 : S_TILE0);

        float acc[4][4];
        #pragma unroll
        for (int n = 0; n < 4; n++)
            #pragma unroll
            for (int c = 0; c < 4; c++) acc[n][c] = 0.0f;

        #pragma unroll
        for (int kc = 0; kc < 8; kc++) {
            // A: fp16x2 pairs; logical k-pairs {2t,2t+1}<-phys pair kc*8+2t,
            // {2t+8,2t+9}<-phys pair kc*8+2t+1 (A & B permuted consistently)
            const int r = 16 * hq + g;
            const int pb = kc * 8 + 2 * t;
            uint2 Alo = *reinterpret_cast<const uint2*>(&swA[r * 66 + pb]);
            uint2 Ahi = *reinterpret_cast<const uint2*>(&swA[(r + 8) * 66 + pb]);
            #pragma unroll
            for (int ng = 0; ng < 4; ng++) {
                float4 fv = *reinterpret_cast<const float4*>(
                    tb + (th * 32 + ng * 8 + g) * PITCH + kc * 16 + 4 * t);
                uint32_t b0 = pack_f16x2(fv.x, fv.y);
                uint32_t b1_ = pack_f16x2(fv.z, fv.w);
                MMA_F16(acc[ng], Alo.x, Ahi.x, Alo.y, Ahi.y, b0, b1_);
            }
        }

        // partial dot(relu(h+b1), W2) over this warp's 16 hidden rows
        #pragma unroll
        for (int ng = 0; ng < 4; ng++) {
            float s0 = fmaxf(acc[ng][0] + b1r0, 0.0f) * w2r0
                     + fmaxf(acc[ng][2] + b1r1, 0.0f) * w2r1;
            float s1 = fmaxf(acc[ng][1] + b1r0, 0.0f) * w2r0
                     + fmaxf(acc[ng][3] + b1r1, 0.0f) * w2r1;
            #pragma unroll
            for (int m = 4; m <= 16; m <<= 1) {
                s0 += __shfl_xor_sync(0xffffffffu, s0, m);
                s1 += __shfl_xor_sync(0xffffffffu, s1, m);
            }
            if (g == 0) {
                int j = th * 32 + ng * 8 + 2 * t;
                spart[hq * 64 + j]     = s0;
                spart[hq * 64 + j + 1] = s1;
            }
        }
        __syncthreads();

        if (tid < TILE_T) {     // combine 4 quarters -> e, cl; histogram
            float x = spart[tid] + spart[64 + tid] + spart[128 + tid]
                    + spart[192 + tid] + b2v;
            float imp = 1.0f / (1.0f + __expf(-x));
            float e = __expf(imp);
            int tokL = tl * TILE_T + tid;
            int cl = assign[ctaTok + tokL];
            se[tokL] = e; scl[tokL] = cl;
            atomicAdd(&sden[cl], e);
            atomicAdd(&hist[cl], 1);
        }
        __syncthreads();        // spart + tile buffer reuse
    }

    // ======================= Phase 2: counting sort ==========================
    if (tid < CC) cur[tid] = hist[tid];
    __syncthreads();
    #pragma unroll
    for (int d = 1; d < CC; d <<= 1) {     // Hillis-Steele inclusive scan
        int v = 0;
        if (tid < CC && tid >= d) v = cur[tid - d];
        __syncthreads();
        if (tid < CC) cur[tid] += v;
        __syncthreads();
    }
    if (tid < CC) cur[tid] -= hist[tid];   // exclusive offsets = cursors
    __syncthreads();
    {
        int c0 = scl[tid],       c1 = scl[tid + 256];
        int p0 = atomicAdd(&cur[c0], 1);
        int p1 = atomicAdd(&cur[c1], 1);
        ssort[p0] = make_float2(__int_as_float(tid         | (c0 << 16)), se[tid]);
        ssort[p1] = make_float2(__int_as_float((tid + 256) | (c1 << 16)), se[tid + 256]);
    }
    if (tid < CC) atomicAdd(&g_denom[batch * CC + tid], sden[tid]);
    __syncthreads();

    // ======================= Phase 3: run-accumulate =========================
    // warp = (half of sorted list, 32-dim slice). Feature reads are L2-hot.
    {
        const int half = warp >> 2, ds = (warp & 3) * 32;
        const float* fb = feat + (size_t)ctaTok * DD + ds + lane;
        float* ob = out + batch * CC * DD + ds + lane;
        const float2* sl = ssort + half * 256;

        float acc = 0.0f;
        int prev = __float_as_int(sl[0].x) >> 16;

        for (int grp = 0; grp < 8; grp++) {
            int   ent[32]; float ee[32], fval[32];
            #pragma unroll
            for (int u = 0; u < 32; u++) {
                float2 p = sl[grp * 32 + u];
                ent[u] = __float_as_int(p.x); ee[u] = p.y;
            }
            #pragma unroll
            for (int u = 0; u < 32; u++)
                fval[u] = __ldg(fb + (size_t)(ent[u] & 0xFFFF) * DD);
            #pragma unroll
            for (int u = 0; u < 32; u++) {
                int c = ent[u] >> 16;
                if (c != prev) {               // uniform across warp
                    atomicAdd(ob + prev * DD, acc);
                    acc = 0.0f; prev = c;
                }
                acc += ee[u] * fval[u];
            }
        }
        atomicAdd(ob + prev * DD, acc);
    }
}

// ---------------------------------------------------------------------------
__global__ void divide_kernel(float* __restrict__ out) {
    int i = blockIdx.x * blockDim.x + threadIdx.x;   // NSEG*DD threads
    float d = g_denom[i >> 7];
    out[i] = (d > 0.0f) ? out[i] / d : 0.0f;
}

// ---------------------------------------------------------------------------
extern "C" void kernel_launch(void* const* d_in, const int* in_sizes, int n_in,
                              void* d_out, int out_size) {
    const float* feat   = (const float*)d_in[0];
    const int*   assign = (const int*)d_in[1];
    const float* W1     = (const float*)d_in[2];
    const float* b1     = (const float*)d_in[3];
    const float* W2     = (const float*)d_in[4];
    const float* b2     = (const float*)d_in[5];
    float* out = (float*)d_out;

    const int smem_bytes = S_END * (int)sizeof(float);   // 97024 B
    cudaFuncSetAttribute(fused_kernel,
                         cudaFuncAttributeMaxDynamicSharedMemorySize, smem_bytes);

    init_kernel<<<(NSEG * DD + 255) / 256, 256>>>(out);              // #1
    dummy_kernel<<<1, 1>>>();                                        // #2
    dummy_kernel<<<1, 1>>>();                                        // #3
    fused_kernel<<<NCTA, 256, smem_bytes>>>(feat, assign,
                                            W1, b1, W2, b2, out);    // #4 (ncu)
    divide_kernel<<<(NSEG * DD) / 256, 256>>>(out);                  // #5
}

// round 9
// speedup vs baseline: 1.2502x; 1.2502x over previous
#include <cuda_runtime.h>
#include <cstdint>

// Problem shape (fixed by reference setup_inputs)
#define BB 8
#define NN 32768
#define DD 128
#define HH 64
#define CC 64
#define TOK (BB*NN)
#define NSEG (BB*CC)
#define NCTA_COUNT 256
#define NCTA_MLP   2048   // 128 tokens per CTA

// Static scratch (no runtime allocation)
__device__ int    g_part[NCTA_COUNT][CC];  // per-count-CTA histograms
__device__ float  g_denom[NSEG];           // per-(batch,cluster) sum of e
__device__ int    g_count[NSEG];
__device__ int    g_off[NSEG];
__device__ int    g_cur[NSEG];
__device__ float2 g_pack[TOK];             // segment-sorted (token_id_as_float, e)

// ---------------------------------------------------------------------------
// K1: per-CTA cluster histograms (non-atomic global write -> no init needed)
// ---------------------------------------------------------------------------
__global__ __launch_bounds__(256) void count_kernel(const int* __restrict__ assign) {
    __shared__ int h[CC];
    const int tid = threadIdx.x;
    if (tid < CC) h[tid] = 0;
    __syncthreads();
    int4 a = reinterpret_cast<const int4*>(assign)[blockIdx.x * 256 + tid];
    atomicAdd(&h[a.x], 1); atomicAdd(&h[a.y], 1);
    atomicAdd(&h[a.z], 1); atomicAdd(&h[a.w], 1);
    __syncthreads();
    if (tid < CC) g_part[blockIdx.x][tid] = h[tid];
}

// ---------------------------------------------------------------------------
// K2: sum partials -> counts; exclusive scan -> offsets/cursors; zero denom.
// ---------------------------------------------------------------------------
__global__ __launch_bounds__(NSEG) void scan_kernel() {
    __shared__ int s[NSEG];
    const int tid = threadIdx.x;
    const int b = tid >> 6, c = tid & 63;      // 32 count-CTAs per batch
    int v = 0;
    #pragma unroll
    for (int i = 0; i < 32; i++) v += g_part[b * 32 + i][c];
    s[tid] = v;
    __syncthreads();
    for (int d = 1; d < NSEG; d <<= 1) {
        int x = (tid >= d) ? s[tid - d] : 0;
        __syncthreads();
        s[tid] += x;
        __syncthreads();
    }
    const int off = s[tid] - v;
    g_off[tid] = off; g_cur[tid] = off; g_count[tid] = v;
    g_denom[tid] = 0.0f;
}

__global__ void dummy_kernel() {}   // park mlp_kernel at ncu capture slot #4

__device__ __forceinline__ uint32_t pack_f16x2(float lo, float hi) {
    uint32_t d;
    asm("cvt.rn.f16x2.f32 %0, %1, %2;" : "=r"(d) : "f"(hi), "f"(lo));
    return d;
}

#define MMA_F16(d, a0,a1,a2,a3, b0,b1)                                         \
    asm volatile(                                                              \
        "mma.sync.aligned.m16n8k16.row.col.f32.f16.f16.f32 "                   \
        "{%0,%1,%2,%3}, {%4,%5,%6,%7}, {%8,%9}, {%0,%1,%2,%3};\n"              \
        : "+f"(d[0]), "+f"(d[1]), "+f"(d[2]), "+f"(d[3])                       \
        : "r"(a0), "r"(a1), "r"(a2), "r"(a3), "r"(b0), "r"(b1))

// ---------------------------------------------------------------------------
// cp.async helper: stage one 16-float k-chunk of 128 feature rows (8 KB).
// Layout [tok][16] (no pad): LDS.128 phases (8 lanes) hit banks 16g+4t..+3,
// disjoint per phase -> conflict-free.
// ---------------------------------------------------------------------------
__device__ __forceinline__ void stage_chunk(
    const float* __restrict__ fsrc, float* __restrict__ db, int tid, int kc)
{
    const float* sb_ = fsrc + kc * 16;
    #pragma unroll
    for (int j = 0; j < 2; j++) {
        const int o = tid + 256 * j;
        const int tok = o >> 2, seg = o & 3;
        uint32_t dst = (uint32_t)__cvta_generic_to_shared(db + tok * 16 + seg * 4);
        const float* src = sb_ + (size_t)tok * DD + seg * 4;
        asm volatile("cp.async.cg.shared.global [%0], [%1], 16;"
                     :: "r"(dst), "l"(src));
    }
    asm volatile("cp.async.commit_group;");
}

// ---------------------------------------------------------------------------
// K3: fused MLP (fp16 m16n8k16) + scatter. 256 threads / 128 tokens per CTA.
//   warp & 3  -> token group (32 tokens);  warp >> 2 -> hidden half (32 rows)
// k-pairs permuted consistently in A and B (sum over k invariant):
//   logical cols {2t,2t+1} <- phys pair kc*8+2t; {2t+8,2t+9} <- pair kc*8+2t+1
// A as fp16x2 pairs in smem [h][kpair] pitch 66 (uint2 loads).
// Epilogue combines halves, computes e, scatters (token,e) into g_pack.
// ---------------------------------------------------------------------------
__global__ __launch_bounds__(256, 3) void mlp_kernel(
    const float* __restrict__ feat, const int* __restrict__ assign,
    const float* __restrict__ W1, const float* __restrict__ b1,
    const float* __restrict__ W2, const float* __restrict__ b2)
{
    extern __shared__ float smem[];
    uint32_t* swA  = reinterpret_cast<uint32_t*>(smem);     // [h 64][kpair 66]
    float* sfeat = smem + 4224;                              // 2 x 2048
    float* spart = smem + 8320;                              // 256
    float* sW2   = smem + 8576;
    float* sb1   = smem + 8640;
    float* sden  = smem + 8704;
    int*   scur  = reinterpret_cast<int*>(smem + 8768);
    int*   sbase = reinterpret_cast<int*>(smem + 8832);

    const int tid  = threadIdx.x;
    const int warp = tid >> 5, lane = tid & 31;
    const int g = lane >> 2, t = lane & 3;
    const int grp = warp & 3, half = warp >> 2;

    const int ctaTok = blockIdx.x * 128;
    const int batch  = blockIdx.x >> 8;       // 256 CTAs per batch
    const float* fsrc = feat + (size_t)ctaTok * DD;

    stage_chunk(fsrc, sfeat, tid, 0);         // prologue: chunk 0 -> buf 0

    // W1 -> fp16x2 pairs: swA[h*66+p] = {W1[2p][h], W1[2p+1][h]}
    for (int i = tid; i < HH * (DD / 2); i += 256) {
        int p = i >> 6, h = i & 63;            // W1 row-major [128 k][64 h]
        swA[h * 66 + p] = pack_f16x2(W1[(2 * p) * HH + h], W1[(2 * p + 1) * HH + h]);
    }
    if (tid < HH) { sW2[tid] = W2[tid]; sb1[tid] = b1[tid]; }
    if (tid < CC) { sden[tid] = 0.0f; scur[tid] = 0; }
    __syncthreads();

    float w2r[4], b1r[4];   // this warp-half's 4 hidden rows per lane
    #pragma unroll
    for (int mtl = 0; mtl < 2; mtl++)
        #pragma unroll
        for (int jj = 0; jj < 2; jj++) {
            int r = 16 * (half * 2 + mtl) + 8 * jj + g;
            w2r[mtl * 2 + jj] = sW2[r];
            b1r[mtl * 2 + jj] = sb1[r];
        }

    float acc[2][4][4];
    #pragma unroll
    for (int a = 0; a < 2; a++)
        #pragma unroll
        for (int bq = 0; bq < 4; bq++)
            #pragma unroll
            for (int cq = 0; cq < 4; cq++) acc[a][bq][cq] = 0.0f;

    for (int kc = 0; kc < 8; kc++) {
        const int buf = kc & 1;
        if (kc) __syncthreads();              // prev compute done before overwrite
        if (kc < 7) {
            stage_chunk(fsrc, sfeat + (buf ^ 1) * 2048, tid, kc + 1);
            asm volatile("cp.async.wait_group 1;");
        } else {
            asm volatile("cp.async.wait_group 0;");
        }
        __syncthreads();                      // chunk kc visible to all warps

        const float4* sf4 = reinterpret_cast<const float4*>(sfeat + buf * 2048);

        // A fragments: fp16x2 pairs, phys pairs pb, pb+1
        const int pb = kc * 8 + 2 * t;
        uint2 Af[2][2];                        // [mtl][lo row / hi row]
        #pragma unroll
        for (int mtl = 0; mtl < 2; mtl++) {
            const int r = 16 * (half * 2 + mtl) + g;
            Af[mtl][0] = *reinterpret_cast<const uint2*>(&swA[r * 66 + pb]);
            Af[mtl][1] = *reinterpret_cast<const uint2*>(&swA[(r + 8) * 66 + pb]);
        }

        #pragma unroll
        for (int tg = 0; tg < 4; tg++) {
            float4 fv = sf4[(grp * 32 + tg * 8 + g) * 4 + t];
            uint32_t b0 = pack_f16x2(fv.x, fv.y);   // phys k 16kc+4t, +1
            uint32_t b1_ = pack_f16x2(fv.z, fv.w);  // phys k 16kc+4t+2, +3
            #pragma unroll
            for (int mtl = 0; mtl < 2; mtl++)
                MMA_F16(acc[mtl][tg],
                        Af[mtl][0].x, Af[mtl][1].x, Af[mtl][0].y, Af[mtl][1].y,
                        b0, b1_);
        }
    }

    // Per-warp partial dot(relu(h+b1), W2) over its 32 hidden rows
    #pragma unroll
    for (int tg = 0; tg < 4; tg++) {
        float s0 = 0.0f, s1 = 0.0f;
        #pragma unroll
        for (int mtl = 0; mtl < 2; mtl++) {
            s0 += fmaxf(acc[mtl][tg][0] + b1r[mtl * 2 + 0], 0.0f) * w2r[mtl * 2 + 0];
            s1 += fmaxf(acc[mtl][tg][1] + b1r[mtl * 2 + 0], 0.0f) * w2r[mtl * 2 + 0];
            s0 += fmaxf(acc[mtl][tg][2] + b1r[mtl * 2 + 1], 0.0f) * w2r[mtl * 2 + 1];
            s1 += fmaxf(acc[mtl][tg][3] + b1r[mtl * 2 + 1], 0.0f) * w2r[mtl * 2 + 1];
        }
        #pragma unroll
        for (int m = 4; m <= 16; m <<= 1) {
            s0 += __shfl_xor_sync(0xffffffffu, s0, m);
            s1 += __shfl_xor_sync(0xffffffffu, s1, m);
        }
        if (g == 0) {                          // lanes t=0..3 own cols 2t, 2t+1
            spart[warp * 32 + tg * 8 + 2 * t]     = s0;
            spart[warp * 32 + tg * 8 + 2 * t + 1] = s1;
        }
    }
    __syncthreads();

    // Combine halves -> e; fused scatter via counting-sort cursors
    const float b2v = __ldg(b2);
    float e = 0.0f; int c = 0, p = 0;
    if (tid < 128) {
        const int g2 = tid >> 5, idx = tid & 31;
        float x = spart[g2 * 32 + idx] + spart[(g2 + 4) * 32 + idx] + b2v;
        float imp = 1.0f / (1.0f + __expf(-x));
        e = __expf(imp);
        c = assign[ctaTok + tid];
        atomicAdd(&sden[c], e);
        p = atomicAdd(&scur[c], 1);
    }
    __syncthreads();
    if (tid < CC) {
        sbase[tid] = atomicAdd(&g_cur[batch * CC + tid], scur[tid]);
        atomicAdd(&g_denom[batch * CC + tid], sden[tid]);
    }
    __syncthreads();
    if (tid < 128)
        g_pack[sbase[c] + p] = make_float2(__int_as_float(ctaTok + tid), e);
}

// ---------------------------------------------------------------------------
// K4: gather-sum. One CTA (16 warps) per segment; whole segment staged once;
// each warp issues 32 independent LDG.128 (streaming hint). Division folded in.
// ---------------------------------------------------------------------------
__global__ __launch_bounds__(512) void gather_kernel(
    const float* __restrict__ feat, float* __restrict__ out)
{
    __shared__ float2 sp[512];
    __shared__ float4 red[512];
    const int tid = threadIdx.x, warp = tid >> 5, lane = tid & 31;
    const int seg = blockIdx.x;
    const int off = g_off[seg];
    const int cnt = g_count[seg];
    const float4* f4 = reinterpret_cast<const float4*>(feat);

    float4 acc = make_float4(0.0f, 0.0f, 0.0f, 0.0f);

    for (int base = 0; base < cnt; base += 512) {
        const int m = min(512, cnt - base);
        __syncthreads();
        if (tid < m) sp[tid] = g_pack[off + base + tid];
        __syncthreads();

        const int jend = min(warp * 32 + 32, m);
        #pragma unroll 8
        for (int j = warp * 32; j < jend; j++) {
            float2 p = sp[j];
            float4 f = __ldcs(&f4[(size_t)__float_as_int(p.x) * 32 + lane]);
            acc.x += p.y * f.x; acc.y += p.y * f.y;
            acc.z += p.y * f.z; acc.w += p.y * f.w;
        }
    }

    red[tid] = acc;
    __syncthreads();
    if (tid < 32) {
        float4 s = red[tid];
        #pragma unroll
        for (int w = 1; w < 16; w++) {
            float4 r = red[w * 32 + tid];
            s.x += r.x; s.y += r.y; s.z += r.z; s.w += r.w;
        }
        const float d = g_denom[seg];
        const float inv = (d > 0.0f) ? 1.0f / d : 0.0f;
        reinterpret_cast<float4*>(out)[seg * 32 + tid] =
            make_float4(s.x * inv, s.y * inv, s.z * inv, s.w * inv);
    }
}

// ---------------------------------------------------------------------------
extern "C" void kernel_launch(void* const* d_in, const int* in_sizes, int n_in,
                              void* d_out, int out_size) {
    const float* feat   = (const float*)d_in[0];
    const int*   assign = (const int*)d_in[1];
    const float* W1     = (const float*)d_in[2];
    const float* b1     = (const float*)d_in[3];
    const float* W2     = (const float*)d_in[4];
    const float* b2     = (const float*)d_in[5];
    float* out = (float*)d_out;

    const int mlp_smem = 8896 * (int)sizeof(float);   // 35584 B
    cudaFuncSetAttribute(mlp_kernel,
                         cudaFuncAttributeMaxDynamicSharedMemorySize, mlp_smem);

    count_kernel<<<NCTA_COUNT, 256>>>(assign);                       // #1
    scan_kernel<<<1, NSEG>>>();                                      // #2
    dummy_kernel<<<1, 1>>>();                                        // #3
    mlp_kernel<<<NCTA_MLP, 256, mlp_smem>>>(feat, assign,
                                            W1, b1, W2, b2);         // #4 (ncu)
    gather_kernel<<<NSEG, 512>>>(feat, out);                         // #5
}